// round 4
// baseline (speedup 1.0000x reference)
#include <cuda_runtime.h>
#include <cuda_bf16.h>

// ---------------------------------------------------------------------------
// GCN: out = log_softmax( A_hat( relu(A_hat(x W1) + b1) W2 ) + b2 )
// A_hat = D^-1/2 (A+I) D^-1/2 applied as per-edge norm = dinv[src]*dinv[dst]
// with scatter-add to dst.
// NOTE: edge_index is int32 on disk (JAX x64 disabled downgrades int64->int32).
// ---------------------------------------------------------------------------

#define N_CAP   50000
#define F_IN    128
#define F_HID   128
#define F_OUT   16

// Scratch (static device globals -- allocation-free rule)
__device__ float g_deg [N_CAP];
__device__ float g_dinv[N_CAP];
__device__ float g_h1  [N_CAP * F_HID];   // x @ W1
__device__ float g_agg1[N_CAP * F_HID];   // scatter result layer 1
__device__ float g_h2  [N_CAP * F_OUT];   // relu(agg1+b1) @ W2

// ---------------------------------------------------------------------------
// vector reduction (no-return atomic add), sm_90+: red.global.add.v4.f32
// ---------------------------------------------------------------------------
__device__ __forceinline__ void red_add_v4(float* addr, float4 v) {
#if defined(__CUDA_ARCH__) && (__CUDA_ARCH__ >= 900)
    asm volatile("red.global.add.v4.f32 [%0], {%1, %2, %3, %4};"
                 :: "l"(addr), "f"(v.x), "f"(v.y), "f"(v.z), "f"(v.w)
                 : "memory");
#else
    atomicAdd(addr + 0, v.x);
    atomicAdd(addr + 1, v.y);
    atomicAdd(addr + 2, v.z);
    atomicAdd(addr + 3, v.w);
#endif
}

// ---------------------------------------------------------------------------
// 0) zero scratch + output
// ---------------------------------------------------------------------------
__global__ void zero_kernel(float* __restrict__ dout, int n, int out_elems) {
    const int stride = gridDim.x * blockDim.x;
    int i = blockIdx.x * blockDim.x + threadIdx.x;
    float4 z = make_float4(0.f, 0.f, 0.f, 0.f);
    for (int k = i; k < n; k += stride) g_deg[k] = 0.f;
    float4* a1 = reinterpret_cast<float4*>(g_agg1);
    int n1 = (n * F_HID) >> 2;
    for (int k = i; k < n1; k += stride) a1[k] = z;
    float4* ov = reinterpret_cast<float4*>(dout);
    int n2 = out_elems >> 2;
    for (int k = i; k < n2; k += stride) ov[k] = z;
}

// ---------------------------------------------------------------------------
// 1) degree: deg[dst] += 1 per edge
// ---------------------------------------------------------------------------
__global__ void deg_kernel(const int* __restrict__ ei, int E) {
    int e = blockIdx.x * blockDim.x + threadIdx.x;
    if (e >= E) return;
    int dst = ei[E + e];
    atomicAdd(&g_deg[dst], 1.0f);   // result unused -> lowers to RED
}

// ---------------------------------------------------------------------------
// 2) dinv = rsqrt(max(deg,1))
// ---------------------------------------------------------------------------
__global__ void dinv_kernel(int n) {
    int i = blockIdx.x * blockDim.x + threadIdx.x;
    if (i >= n) return;
    g_dinv[i] = rsqrtf(fmaxf(g_deg[i], 1.0f));
}

// ---------------------------------------------------------------------------
// 3) GEMM1: h1[n,128] = x[n,128] @ W1[128,128]   (fp32, register-tiled)
//    block: 256 threads -> 64 rows x 128 cols tile; thread: 4 rows x 8 cols
// ---------------------------------------------------------------------------
__global__ __launch_bounds__(256) void gemm1_kernel(
        const float* __restrict__ x, const float* __restrict__ W, int n) {
    __shared__ float Xs[64][33];      // +1 pad: conflict-free column reads
    __shared__ float Ws[32][128];

    const int tid = threadIdx.x;
    const int tx  = tid & 15;         // 16 col-groups (8 cols each)
    const int ty  = tid >> 4;         // 16 row-groups (rows ty, ty+16, ty+32, ty+48)
    const int rowBase = blockIdx.x * 64;

    float acc[4][8];
    #pragma unroll
    for (int r = 0; r < 4; r++)
        #pragma unroll
        for (int j = 0; j < 8; j++) acc[r][j] = 0.f;

    for (int kb = 0; kb < F_IN; kb += 32) {
        // load X tile 64x32 (2 float4 per thread)
        #pragma unroll
        for (int i = 0; i < 2; i++) {
            int f4 = tid * 2 + i;
            int r  = f4 >> 3;
            int c  = (f4 & 7) << 2;
            int grow = rowBase + r;
            float4 v = (grow < n)
                ? *reinterpret_cast<const float4*>(x + (size_t)grow * F_IN + kb + c)
                : make_float4(0.f, 0.f, 0.f, 0.f);
            Xs[r][c]     = v.x;
            Xs[r][c + 1] = v.y;
            Xs[r][c + 2] = v.z;
            Xs[r][c + 3] = v.w;
        }
        // load W tile 32x128 (4 float4 per thread, coalesced)
        #pragma unroll
        for (int i = 0; i < 4; i++) {
            int f4 = tid + i * 256;
            int r  = f4 >> 5;
            int c  = (f4 & 31) << 2;
            *reinterpret_cast<float4*>(&Ws[r][c]) =
                *reinterpret_cast<const float4*>(W + (size_t)(kb + r) * F_HID + c);
        }
        __syncthreads();

        #pragma unroll
        for (int k = 0; k < 32; k++) {
            float b[8];
            *reinterpret_cast<float4*>(&b[0]) = *reinterpret_cast<float4*>(&Ws[k][tx * 8]);
            *reinterpret_cast<float4*>(&b[4]) = *reinterpret_cast<float4*>(&Ws[k][tx * 8 + 4]);
            #pragma unroll
            for (int r = 0; r < 4; r++) {
                float a = Xs[ty + r * 16][k];
                #pragma unroll
                for (int j = 0; j < 8; j++) acc[r][j] += a * b[j];
            }
        }
        __syncthreads();
    }

    #pragma unroll
    for (int r = 0; r < 4; r++) {
        int grow = rowBase + ty + r * 16;
        if (grow < n) {
            float* op = g_h1 + (size_t)grow * F_HID + tx * 8;
            *reinterpret_cast<float4*>(op)     = make_float4(acc[r][0], acc[r][1], acc[r][2], acc[r][3]);
            *reinterpret_cast<float4*>(op + 4) = make_float4(acc[r][4], acc[r][5], acc[r][6], acc[r][7]);
        }
    }
}

// ---------------------------------------------------------------------------
// 4) scatter1: agg1[dst] += h1[src] * norm   (warp per edge, 4 floats/lane)
// ---------------------------------------------------------------------------
__global__ __launch_bounds__(256) void scatter1_kernel(
        const int* __restrict__ ei, int E) {
    int warpId = (blockIdx.x * blockDim.x + threadIdx.x) >> 5;
    int lane   = threadIdx.x & 31;
    if (warpId >= E) return;
    int src = ei[warpId];
    int dst = ei[E + warpId];
    float norm = g_dinv[src] * g_dinv[dst];
    float4 v = reinterpret_cast<const float4*>(g_h1 + (size_t)src * F_HID)[lane];
    v.x *= norm; v.y *= norm; v.z *= norm; v.w *= norm;
    red_add_v4(g_agg1 + (size_t)dst * F_HID + lane * 4, v);
}

// ---------------------------------------------------------------------------
// 5) GEMM2 fused: h2[n,16] = relu(agg1 + b1) @ W2[128,16]
//    block: 256 threads = 16 rows x 16 cols; W2 + b1 + H tile in smem
// ---------------------------------------------------------------------------
__global__ __launch_bounds__(256) void gemm2_kernel(
        const float* __restrict__ b1, const float* __restrict__ W2, int n) {
    __shared__ float Ws[F_HID * F_OUT];   // 2048
    __shared__ float bs[F_HID];
    __shared__ float Hs[16][F_HID];       // 16 rows tile

    const int tid = threadIdx.x;
    for (int i = tid; i < F_HID * F_OUT; i += 256) Ws[i] = W2[i];
    if (tid < F_HID) bs[tid] = b1[tid];

    int rowBase = blockIdx.x * 16;
    // load 16 rows of agg1 (512 float4 / 256 threads = 2 each)
    #pragma unroll
    for (int i = 0; i < 2; i++) {
        int f4 = tid + i * 256;
        int r  = f4 >> 5;           // 32 float4 per row
        int c  = (f4 & 31) << 2;
        int grow = rowBase + r;
        float4 v = (grow < n)
            ? *reinterpret_cast<const float4*>(g_agg1 + (size_t)grow * F_HID + c)
            : make_float4(0.f, 0.f, 0.f, 0.f);
        *reinterpret_cast<float4*>(&Hs[r][c]) = v;
    }
    __syncthreads();

    int j  = tid & 15;
    int rl = tid >> 4;
    int row = rowBase + rl;
    if (row >= n) return;

    float acc = 0.f;
    #pragma unroll
    for (int k = 0; k < F_HID; k++) {
        float h = fmaxf(Hs[rl][k] + bs[k], 0.f);
        acc += h * Ws[k * F_OUT + j];
    }
    g_h2[(size_t)row * F_OUT + j] = acc;
}

// ---------------------------------------------------------------------------
// 6) scatter2: out[dst] += h2[src] * norm   (4 threads per edge, 4 floats each)
// ---------------------------------------------------------------------------
__global__ __launch_bounds__(256) void scatter2_kernel(
        const int* __restrict__ ei, float* __restrict__ out, int E) {
    int t = blockIdx.x * blockDim.x + threadIdx.x;
    int e = t >> 2;
    int q = t & 3;
    if (e >= E) return;
    int src = ei[e];
    int dst = ei[E + e];
    float norm = g_dinv[src] * g_dinv[dst];
    float4 v = reinterpret_cast<const float4*>(g_h2 + (size_t)src * F_OUT)[q];
    v.x *= norm; v.y *= norm; v.z *= norm; v.w *= norm;
    red_add_v4(out + (size_t)dst * F_OUT + q * 4, v);
}

// ---------------------------------------------------------------------------
// 7) log_softmax rows (adds b2); one thread per row (16 cols)
// ---------------------------------------------------------------------------
__global__ void lsm_kernel(float* __restrict__ out, const float* __restrict__ b2, int n) {
    int row = blockIdx.x * blockDim.x + threadIdx.x;
    if (row >= n) return;
    float v[F_OUT];
    float4* p = reinterpret_cast<float4*>(out + (size_t)row * F_OUT);
    #pragma unroll
    for (int i = 0; i < 4; i++) {
        float4 t = p[i];
        v[i * 4 + 0] = t.x + b2[i * 4 + 0];
        v[i * 4 + 1] = t.y + b2[i * 4 + 1];
        v[i * 4 + 2] = t.z + b2[i * 4 + 2];
        v[i * 4 + 3] = t.w + b2[i * 4 + 3];
    }
    float m = v[0];
    #pragma unroll
    for (int i = 1; i < F_OUT; i++) m = fmaxf(m, v[i]);
    float s = 0.f;
    #pragma unroll
    for (int i = 0; i < F_OUT; i++) s += expf(v[i] - m);
    float l = m + logf(s);
    #pragma unroll
    for (int i = 0; i < 4; i++)
        p[i] = make_float4(v[i*4+0] - l, v[i*4+1] - l, v[i*4+2] - l, v[i*4+3] - l);
}

// ---------------------------------------------------------------------------
// launch
// ---------------------------------------------------------------------------
extern "C" void kernel_launch(void* const* d_in, const int* in_sizes, int n_in,
                              void* d_out, int out_size) {
    const float* x  = (const float*)d_in[0];
    const int*   ei = (const int*)d_in[1];      // int32 (JAX x64 disabled)
    const float* W1 = (const float*)d_in[2];
    const float* b1 = (const float*)d_in[3];
    const float* W2 = (const float*)d_in[4];
    const float* b2 = (const float*)d_in[5];
    float* out = (float*)d_out;

    const int n = in_sizes[0] / F_IN;       // 50000
    const int E = in_sizes[1] / 2;          // 850000

    zero_kernel<<<2048, 256>>>(out, n, out_size);
    deg_kernel<<<(E + 255) / 256, 256>>>(ei, E);
    dinv_kernel<<<(n + 255) / 256, 256>>>(n);
    gemm1_kernel<<<(n + 63) / 64, 256>>>(x, W1, n);
    scatter1_kernel<<<(E + 7) / 8, 256>>>(ei, E);           // 8 warps/block
    gemm2_kernel<<<(n + 15) / 16, 256>>>(b1, W2, n);
    scatter2_kernel<<<(E * 4 + 255) / 256, 256>>>(ei, out, E);
    lsm_kernel<<<(n + 255) / 256, 256>>>(out, b2, n);
}